// round 16
// baseline (speedup 1.0000x reference)
#include <cuda_runtime.h>
#include <cuda_bf16.h>

#define VSA_N    2048
#define VSA_BLK  512           // 16 warps
#define VSA_ROWS 16            // rows per block; lane l -> row (l & 15)
#define VSA_STRIDE 65          // padded stream stride (kills half-warp bank conflict)

// ---------------------------------------------------------------------------
// Fused kernel. grid = (128, B), 512 threads (16 warps), R14 structure:
//   * lane l owns row i = bx*16 + (l & 15)
//   * j-stream s = warp*2 + (l >> 4) covers j in [s*64, s*64+64)
//   * tile padded: stream s at sk[s*65 .. s*65+63]; the two half-warp
//     addresses now differ by 65*16 B -> banks offset by 4 -> NO conflict
//     (previously 1024 B apart = same banks = replay every iteration).
//
// R15 calibration: kernel is issue-slot bound at ~0.65us per inst/warp-iter.
// This round removes slots, not structure:
//   Phase A: 9x LDG.128 + class-rotation sums (was 36 LDG.32 + 36 FADD)
//   Phase B: 3x LDG.128 per thread feeding 4 j's (was 12 LDG.32)
//   hot loop: unchanged R14 math (ex2 path), unroll 4.
// ---------------------------------------------------------------------------
__global__ __launch_bounds__(VSA_BLK, 4)
void vsa_fused_kernel(const float* __restrict__ q,
                      const float* __restrict__ k,
                      const float* __restrict__ v,
                      float* __restrict__ out) {
    __shared__ float4 sk[32 * VSA_STRIDE];   // 33280 B; reused for partials
    __shared__ float  red[VSA_BLK / 32][9];
    __shared__ float  means[9];

    const int tid  = threadIdx.x;
    const int b    = blockIdx.y;
    const int warp = tid >> 5;
    const int lane = tid & 31;

    const float* qb = q + (size_t)b * VSA_N * 3;
    const float* kb = k + (size_t)b * VSA_N * 3;
    const float* vb = v + (size_t)b * VSA_N * 3;

    // ---- Phase A: per-batch means, vectorized float4 loads ----
    // Each array is 1536 float4; thread t loads f4[3t], f4[3t+1], f4[3t+2]
    // (one of each alignment class: class c starts at component c (mod 3)).
    {
        const float4* q4 = (const float4*)qb;
        const float4* k4 = (const float4*)kb;
        const float4* v4 = (const float4*)vb;
        const int base = 3 * tid;

        float s[9];
        {
            const float4 a0 = q4[base + 0];   // (x y z x)
            const float4 a1 = q4[base + 1];   // (y z x y)
            const float4 a2 = q4[base + 2];   // (z x y z)
            s[0] = a0.x + a0.w + a1.z + a2.y;
            s[1] = a0.y + a1.x + a1.w + a2.z;
            s[2] = a0.z + a1.y + a2.x + a2.w;
        }
        {
            const float4 a0 = k4[base + 0];
            const float4 a1 = k4[base + 1];
            const float4 a2 = k4[base + 2];
            s[3] = a0.x + a0.w + a1.z + a2.y;
            s[4] = a0.y + a1.x + a1.w + a2.z;
            s[5] = a0.z + a1.y + a2.x + a2.w;
        }
        {
            const float4 a0 = v4[base + 0];
            const float4 a1 = v4[base + 1];
            const float4 a2 = v4[base + 2];
            s[6] = a0.x + a0.w + a1.z + a2.y;
            s[7] = a0.y + a1.x + a1.w + a2.z;
            s[8] = a0.z + a1.y + a2.x + a2.w;
        }

#pragma unroll
        for (int c = 0; c < 9; c++) {
#pragma unroll
            for (int off = 16; off > 0; off >>= 1)
                s[c] += __shfl_xor_sync(0xFFFFFFFFu, s[c], off);
        }
        if (lane == 0) {
#pragma unroll
            for (int c = 0; c < 9; c++) red[warp][c] = s[c];
        }
        __syncthreads();
        if (tid < 9) {
            float t = 0.0f;
#pragma unroll
            for (int w = 0; w < VSA_BLK / 32; w++) t += red[w][tid];
            means[tid] = t * (1.0f / (float)VSA_N);
        }
        __syncthreads();
    }

    const float mqx = means[0], mqy = means[1], mqz = means[2];
    const float mkx = means[3], mky = means[4], mkz = means[5];
    const float mvx = means[6], mvy = means[7], mvz = means[8];

    // c1 = log2(e) / sqrt(2048)  (exp2 path: e = ex2(sqrt(n2')))
    const float c1 = 1.4426950408889634f * 0.022097086912079612f;

    // ---- Phase B: stage k' = (k-mk)*c1 as float4 (xyz, |k'|^2), padded ----
    // Thread t owns j = 4t..4t+3 via 3 LDG.128 (floats [12t, 12t+12)).
    {
        const float4* k4 = (const float4*)kb;
        const int base = 3 * tid;
        const float4 d0 = k4[base + 0];
        const float4 d1 = k4[base + 1];
        const float4 d2 = k4[base + 2];

        float jx[4], jy[4], jz[4];
        jx[0] = d0.x; jy[0] = d0.y; jz[0] = d0.z;
        jx[1] = d0.w; jy[1] = d1.x; jz[1] = d1.y;
        jx[2] = d1.z; jy[2] = d1.w; jz[2] = d2.x;
        jx[3] = d2.y; jy[3] = d2.z; jz[3] = d2.w;

#pragma unroll
        for (int u = 0; u < 4; u++) {
            const int j = 4 * tid + u;
            const float kx = (jx[u] - mkx) * c1;
            const float ky = (jy[u] - mky) * c1;
            const float kz = (jz[u] - mkz) * c1;
            const float kk = fmaf(kx, kx, fmaf(ky, ky, kz * kz));
            sk[(j >> 6) * VSA_STRIDE + (j & 63)] = make_float4(kx, ky, kz, kk);
        }
    }
    __syncthreads();

    // ---- Phase C: hot loop (R14 math, conflict-free padded tile) ----
    const int row    = lane & 15;
    const int stream = warp * 2 + (lane >> 4);   // 0..31
    const int i      = blockIdx.x * VSA_ROWS + row;

    const float qx = qb[i * 3 + 0] - mqx;
    const float qy = qb[i * 3 + 1] - mqy;
    const float qz = qb[i * 3 + 2] - mqz;
    const float qq = fmaf(qx, qx, fmaf(qy, qy, qz * qz));

    float Z = 0.0f, Wx = 0.0f, Wy = 0.0f, Wz = 0.0f;

    const float4* pj = sk + stream * VSA_STRIDE;
#pragma unroll 4
    for (int jj = 0; jj < 64; jj++) {
        const float4 f = pj[jj];   // half-warp broadcast, banks disjoint now
        const float dot = fmaf(qx, f.x, fmaf(qy, f.y, qz * f.z));
        const float n2 = fabsf(fmaf(-dot, dot, qq * f.w));
        float e;
        asm("sqrt.approx.f32 %0, %1;" : "=f"(e) : "f"(n2));
        asm("ex2.approx.f32 %0, %1;"  : "=f"(e) : "f"(e));
        Z += e;
        Wx = fmaf(e, f.x, Wx);
        Wy = fmaf(e, f.y, Wy);
        Wz = fmaf(e, f.z, Wz);
    }

    // ---- Phase D: reduce 32 stream-partials per row ----
    __syncthreads();   // all warps done reading sk
    float4* part = sk;                       // part[stream*17 + row]
    part[stream * 17 + row] = make_float4(Z, Wx, Wy, Wz);
    __syncthreads();

    if (warp < VSA_ROWS) {
        const float4 p = part[lane * 17 + warp];
        float Zr = p.x, Wxr = p.y, Wyr = p.z, Wzr = p.w;
#pragma unroll
        for (int off = 16; off > 0; off >>= 1) {
            Zr  += __shfl_xor_sync(0xFFFFFFFFu, Zr,  off);
            Wxr += __shfl_xor_sync(0xFFFFFFFFu, Wxr, off);
            Wyr += __shfl_xor_sync(0xFFFFFFFFu, Wyr, off);
            Wzr += __shfl_xor_sync(0xFFFFFFFFu, Wzr, off);
        }

        if (lane == 0) {
            const int ir = blockIdx.x * VSA_ROWS + warp;
            const float qxr = qb[ir * 3 + 0] - mqx;
            const float qyr = qb[ir * 3 + 1] - mqy;
            const float qzr = qb[ir * 3 + 2] - mqz;
            // T' = q x W (= c1 * T);  u = cross(T, v_c) / (Z * N)
            const float Tx = fmaf(qyr, Wzr, -qzr * Wyr);
            const float Ty = fmaf(qzr, Wxr, -qxr * Wzr);
            const float Tz = fmaf(qxr, Wyr, -qyr * Wxr);
            const float vx = vb[ir * 3 + 0] - mvx;
            const float vy = vb[ir * 3 + 1] - mvy;
            const float vz = vb[ir * 3 + 2] - mvz;
            const float inv = 1.0f / (Zr * (float)VSA_N * c1);
            float* o = out + ((size_t)b * VSA_N + ir) * 3;
            o[0] = fmaf(Ty, vz, -Tz * vy) * inv;
            o[1] = fmaf(Tz, vx, -Tx * vz) * inv;
            o[2] = fmaf(Tx, vy, -Ty * vx) * inv;
        }
    }
}

// ---------------------------------------------------------------------------
extern "C" void kernel_launch(void* const* d_in, const int* in_sizes, int n_in,
                              void* d_out, int out_size) {
    const float* q = (const float*)d_in[0];
    const float* k = (const float*)d_in[1];
    const float* v = (const float*)d_in[2];
    float* out = (float*)d_out;

    const int B = out_size / (VSA_N * 3);   // = 4

    dim3 grid(VSA_N / VSA_ROWS, B);         // (128, 4) = 512 blocks
    vsa_fused_kernel<<<grid, VSA_BLK>>>(q, k, v, out);
}